// round 2
// baseline (speedup 1.0000x reference)
#include <cuda_runtime.h>
#include <math.h>

#define Bn 64
#define Tn 512
#define Xn 8
#define Hn 128
#define K3 384   // 3*H

// -------- device scratch (allocation-free: __device__ globals) --------
__device__ float g_Pw[(size_t)Bn * Tn * Xn * K3];  // 402 MB  [B,T,X,3H]
__device__ float g_Pc[(size_t)Bn * Tn * K3];       // 50 MB   [B,T,3H]
__device__ float g_Pa[(size_t)Bn * Tn * Hn];       // 17 MB   [B,T,H]

// ---------------------------------------------------------------------
// Generic C[M,N] = A[M,128] @ W[128,N] + bias[N], fp32.
// BM=64, BN=64, BK=16, 256 threads, 4x4 microtile per thread.
// M, N are multiples of 64 here.
// ---------------------------------------------------------------------
__global__ __launch_bounds__(256) void gemm_k128(
    const float* __restrict__ A, const float* __restrict__ W,
    const float* __restrict__ bias, float* __restrict__ C, int N)
{
    __shared__ float As[16][64];  // [k][m]
    __shared__ float Ws[16][64];  // [k][n]

    const int m0 = blockIdx.y * 64;
    const int n0 = blockIdx.x * 64;
    const int tid = threadIdx.x;

    const int ar = tid >> 2;            // 0..63  (A row in tile)
    const int ac = (tid & 3) << 2;      // 0,4,8,12 (k quad)
    const int wr = tid >> 4;            // 0..15  (W k-row)
    const int wc = (tid & 15) << 2;     // 0..60  (n quad)
    const int tm = (tid >> 4) << 2;     // 0..60
    const int tn = (tid & 15) << 2;     // 0..60

    float acc[4][4];
#pragma unroll
    for (int i = 0; i < 4; i++)
#pragma unroll
        for (int j = 0; j < 4; j++) acc[i][j] = 0.f;

    const float* Ag = A + (size_t)m0 * 128;

    for (int kc = 0; kc < 128; kc += 16) {
        float4 av = *(const float4*)(Ag + (size_t)ar * 128 + kc + ac);
        As[ac + 0][ar] = av.x;
        As[ac + 1][ar] = av.y;
        As[ac + 2][ar] = av.z;
        As[ac + 3][ar] = av.w;
        float4 wv = *(const float4*)(W + (size_t)(kc + wr) * N + n0 + wc);
        *(float4*)&Ws[wr][wc] = wv;
        __syncthreads();

#pragma unroll
        for (int k = 0; k < 16; k++) {
            float af[4], bf[4];
            *(float4*)af = *(const float4*)&As[k][tm];
            *(float4*)bf = *(const float4*)&Ws[k][tn];
#pragma unroll
            for (int i = 0; i < 4; i++)
#pragma unroll
                for (int j = 0; j < 4; j++) acc[i][j] = fmaf(af[i], bf[j], acc[i][j]);
        }
        __syncthreads();
    }

    float bv[4];
#pragma unroll
    for (int j = 0; j < 4; j++) bv[j] = bias[n0 + tn + j];
#pragma unroll
    for (int i = 0; i < 4; i++) {
        float4 o;
        o.x = acc[i][0] + bv[0];
        o.y = acc[i][1] + bv[1];
        o.z = acc[i][2] + bv[2];
        o.w = acc[i][3] + bv[3];
        *(float4*)&C[(size_t)(m0 + tm + i) * N + n0 + tn] = o;
    }
}

__device__ __forceinline__ float sigm(float x) { return 1.f / (1.f + expf(-x)); }

// ---------------------------------------------------------------------
// Recurrent kernel: one CTA per batch element, 384 threads, loop over T.
// History = the output buffer itself (hs/cs), slot s+1 == hs[b][s].
// ---------------------------------------------------------------------
__global__ __launch_bounds__(384, 1) void lattice_recurrent(
    const float* __restrict__ whhw,   // [128,384]
    const float* __restrict__ whhc,   // [128,384]
    const float* __restrict__ ahh,    // [128,128]
    const int*   __restrict__ srcp,   // [B,T,X]
    const int*   __restrict__ cntp,   // [B,T]
    float* __restrict__ out)          // hs then cs, each [B,T,H]
{
    const int b = blockIdx.x;
    const int tid = threadIdx.x;

    float* hs = out;
    float* cs = out + (size_t)Bn * Tn * Hn;

    __shared__ float hx_s[Xn][Hn];
    __shared__ float cx_s[Xn][Hn];
    __shared__ float h0_s[Hn];
    __shared__ float gws[9][K3];
    __shared__ float c1s[Xn][Hn];
    __shared__ float alphas[Xn][Hn];
    __shared__ float ig_s[Hn], og_s[Hn], gg_s[Hn];
    __shared__ int js[Xn];

    for (int t = 0; t < Tn; t++) {
        const int cn = cntp[b * Tn + t];
        if (tid < Xn) js[tid] = srcp[(b * Tn + t) * Xn + tid];
        __syncthreads();

        // ---- phase 0: gather history rows + h0 ----
        for (int i = tid; i < Xn * Hn; i += 384) {
            const int x = i >> 7, h = i & 127;
            const int s = js[x];  // slot (s+1) == hs[b][s]
            hx_s[x][h] = hs[((size_t)b * Tn + s) * Hn + h];
            cx_s[x][h] = cs[((size_t)b * Tn + s) * Hn + h];
        }
        if (tid < Hn)
            h0_s[tid] = (t == 0) ? 0.f : hs[((size_t)b * Tn + t - 1) * Hn + tid];
        __syncthreads();

        // ---- phase 1: gw (8 rows) + gc (row 8), one column per thread ----
        {
            const int col = tid;  // 0..383
            float acc[9];
            const float* pw = g_Pw + ((size_t)(b * Tn + t) * Xn) * K3 + col;
#pragma unroll
            for (int x = 0; x < 8; x++) acc[x] = pw[x * K3];
            acc[8] = g_Pc[(size_t)(b * Tn + t) * K3 + col];

#pragma unroll 4
            for (int k = 0; k < 128; k++) {
                const float wv = whhw[k * K3 + col];
                const float wc = whhc[k * K3 + col];
#pragma unroll
                for (int x = 0; x < 8; x++) acc[x] = fmaf(hx_s[x][k], wv, acc[x]);
                acc[8] = fmaf(h0_s[k], wc, acc[8]);
            }
#pragma unroll
            for (int r = 0; r < 9; r++) gws[r][col] = acc[r];
        }
        __syncthreads();

        // ---- phase 2: gates -> c1_skip, i/o/g gates ----
        if (tid < Hn) {
            const int h = tid;
            ig_s[h] = sigm(gws[8][h]);
            og_s[h] = sigm(gws[8][h + 128]);
            gg_s[h] = tanhf(gws[8][h + 256]);
#pragma unroll
            for (int x = 0; x < 8; x++) {
                const float fg = sigm(gws[x][h]);
                const float iw = sigm(gws[x][h + 128]);
                const float gg = tanhf(gws[x][h + 256]);
                c1s[x][h] = fg * cx_s[x][h] + iw * gg;
            }
        }
        __syncthreads();

        // ---- phase 3: alpha = sigmoid(P_a + c1_skip @ a_hh) ----
        for (int o = tid; o < Xn * Hn; o += 384) {
            const int x = o >> 7, h = o & 127;
            float s = g_Pa[(size_t)(b * Tn + t) * Hn + h];
#pragma unroll 4
            for (int k = 0; k < 128; k++) s = fmaf(c1s[x][k], ahh[k * Hn + h], s);
            alphas[x][h] = sigm(s);
        }
        __syncthreads();

        // ---- phase 4: masked softmax merge, write h1/c1 ----
        if (tid < Hn) {
            const int h = tid;
            const float e0 = expf(ig_s[h]);
            float den = e0;
            float num = gg_s[h] * e0;
#pragma unroll
            for (int x = 0; x < 8; x++) {
                if (x < cn) {
                    const float ea = expf(alphas[x][h]);
                    den += ea;
                    num += c1s[x][h] * ea;
                }
            }
            const float c1 = num / den;
            hs[((size_t)b * Tn + t) * Hn + h] = og_s[h] * tanhf(c1);
            cs[((size_t)b * Tn + t) * Hn + h] = c1;
        }
        __syncthreads();
    }
}

// ---------------------------------------------------------------------
extern "C" void kernel_launch(void* const* d_in, const int* in_sizes, int n_in,
                              void* d_out, int out_size)
{
    // Resolve input ordering: dict order has seq_len (size 64) at index 2.
    int i_src, i_cnt, i_wihc, i_whhc, i_bc, i_aih, i_ahh, i_ab, i_wihw, i_whhw, i_bw;
    if (in_sizes[2] == Bn) {
        // setup_inputs dict order
        i_src = 3;  i_cnt = 4;
        i_wihc = 5; i_whhc = 6; i_bc = 7;
        i_aih = 8;  i_ahh = 9;  i_ab = 10;
        i_wihw = 11; i_whhw = 12; i_bw = 13;
    } else {
        // reference() signature order
        i_wihc = 2; i_whhc = 3; i_bc = 4;
        i_aih = 5;  i_ahh = 6;  i_ab = 7;
        i_wihw = 8; i_whhw = 9; i_bw = 10;
        i_src = 12; i_cnt = 13;
    }

    const float* inp        = (const float*)d_in[0];
    const float* skip_words = (const float*)d_in[1];
    const int*   srcp       = (const int*)d_in[i_src];
    const int*   cntp       = (const int*)d_in[i_cnt];
    const float* wihc = (const float*)d_in[i_wihc];
    const float* whhc = (const float*)d_in[i_whhc];
    const float* bc   = (const float*)d_in[i_bc];
    const float* aih  = (const float*)d_in[i_aih];
    const float* ahh  = (const float*)d_in[i_ahh];
    const float* ab   = (const float*)d_in[i_ab];
    const float* wihw = (const float*)d_in[i_wihw];
    const float* whhw = (const float*)d_in[i_whhw];
    const float* bw   = (const float*)d_in[i_bw];

    float *Pw, *Pc, *Pa;
    cudaGetSymbolAddress((void**)&Pw, g_Pw);
    cudaGetSymbolAddress((void**)&Pc, g_Pc);
    cudaGetSymbolAddress((void**)&Pa, g_Pa);

    // Precompute input projections (fully parallel GEMMs, K=128)
    gemm_k128<<<dim3(K3 / 64, (Bn * Tn * Xn) / 64), 256>>>(skip_words, wihw, bw, Pw, K3);
    gemm_k128<<<dim3(K3 / 64, (Bn * Tn) / 64),      256>>>(inp,        wihc, bc, Pc, K3);
    gemm_k128<<<dim3(Hn / 64, (Bn * Tn) / 64),      256>>>(inp,        aih,  ab, Pa, Hn);

    // Recurrent scan: one CTA per batch element
    lattice_recurrent<<<Bn, 384>>>(whhw, whhc, ahh, srcp, cntp, (float*)d_out);
}

// round 3
// speedup vs baseline: 1.6663x; 1.6663x over previous
#include <cuda_runtime.h>
#include <math.h>
#include <stdint.h>

#define Bn 64
#define Tn 512
#define Xn 8
#define Hn 128
#define K3 384   // 3*H

// -------- device scratch (allocation-free) --------
__device__ float g_Pw[(size_t)Bn * Tn * Xn * K3];  // [B,T,X,3H]
__device__ float g_Pc[(size_t)Bn * Tn * K3];       // [B,T,3H]
__device__ float g_Pa[(size_t)Bn * Tn * Hn];       // [B,T,H]

// -------- cp.async helpers --------
__device__ __forceinline__ void cpa16(uint32_t s, const void* g) {
    asm volatile("cp.async.cg.shared.global [%0], [%1], 16;" :: "r"(s), "l"(g));
}
__device__ __forceinline__ void cp_commit() { asm volatile("cp.async.commit_group;"); }
template<int N> __device__ __forceinline__ void cp_wait() {
    asm volatile("cp.async.wait_group %0;" :: "n"(N));
}

__device__ __forceinline__ float sigm(float x) { return 1.f / (1.f + expf(-x)); }

// ---------------------------------------------------------------------
// SGEMM: C[M,N] = A[M,128] @ W[128,N] + bias[N].  128x128 tile, BK=8,
// 256 threads, 8x8 microtile, double-buffered smem.  M,N % 128 == 0.
// ---------------------------------------------------------------------
__global__ __launch_bounds__(256) void gemm128(
    const float* __restrict__ A, const float* __restrict__ W,
    const float* __restrict__ bias, float* __restrict__ C, int N)
{
    __shared__ float As[2][8][128];   // [k][m]
    __shared__ float Bs[2][8][128];   // [k][n]

    const int tid = threadIdx.x;
    const int m0 = blockIdx.y * 128;
    const int n0 = blockIdx.x * 128;

    const int arow = tid >> 1;            // 0..127
    const int ak4  = (tid & 1) << 2;      // 0 or 4
    const int brow = tid >> 5;            // 0..7
    const int bc4  = (tid & 31) << 2;     // 0..124
    const int ty   = tid >> 4;            // 0..15
    const int tx   = tid & 15;            // 0..15

    const float* Ag = A + (size_t)(m0 + arow) * 128 + ak4;
    const float* Wg = W + (size_t)brow * N + n0 + bc4;

    float acc[8][8];
#pragma unroll
    for (int i = 0; i < 8; i++)
#pragma unroll
        for (int j = 0; j < 8; j++) acc[i][j] = 0.f;

    float4 ra = *(const float4*)Ag;
    float4 rb = *(const float4*)Wg;
    As[0][ak4 + 0][arow] = ra.x;
    As[0][ak4 + 1][arow] = ra.y;
    As[0][ak4 + 2][arow] = ra.z;
    As[0][ak4 + 3][arow] = ra.w;
    *(float4*)&Bs[0][brow][bc4] = rb;
    __syncthreads();

    int p = 0;
    for (int kc = 8; kc <= 128; kc += 8) {
        const bool more = (kc < 128);
        if (more) {
            ra = *(const float4*)(Ag + kc);
            rb = *(const float4*)(Wg + (size_t)kc * N);
        }
#pragma unroll
        for (int k = 0; k < 8; k++) {
            float af[8], bf[8];
            *(float4*)&af[0] = *(const float4*)&As[p][k][ty * 4];
            *(float4*)&af[4] = *(const float4*)&As[p][k][ty * 4 + 64];
            *(float4*)&bf[0] = *(const float4*)&Bs[p][k][tx * 4];
            *(float4*)&bf[4] = *(const float4*)&Bs[p][k][tx * 4 + 64];
#pragma unroll
            for (int i = 0; i < 8; i++)
#pragma unroll
                for (int j = 0; j < 8; j++) acc[i][j] = fmaf(af[i], bf[j], acc[i][j]);
        }
        if (more) {
            p ^= 1;
            As[p][ak4 + 0][arow] = ra.x;
            As[p][ak4 + 1][arow] = ra.y;
            As[p][ak4 + 2][arow] = ra.z;
            As[p][ak4 + 3][arow] = ra.w;
            *(float4*)&Bs[p][brow][bc4] = rb;
            __syncthreads();
        }
    }

    float bv[8];
#pragma unroll
    for (int j = 0; j < 4; j++) {
        bv[j]     = bias[n0 + tx * 4 + j];
        bv[j + 4] = bias[n0 + tx * 4 + 64 + j];
    }
#pragma unroll
    for (int i = 0; i < 8; i++) {
        const int r = m0 + ty * 4 + (i & 3) + ((i >> 2) << 6);
        float4 o0, o1;
        o0.x = acc[i][0] + bv[0]; o0.y = acc[i][1] + bv[1];
        o0.z = acc[i][2] + bv[2]; o0.w = acc[i][3] + bv[3];
        o1.x = acc[i][4] + bv[4]; o1.y = acc[i][5] + bv[5];
        o1.z = acc[i][6] + bv[6]; o1.w = acc[i][7] + bv[7];
        *(float4*)&C[(size_t)r * N + n0 + tx * 4]      = o0;
        *(float4*)&C[(size_t)r * N + n0 + tx * 4 + 64] = o1;
    }
}

// ---------------------------------------------------------------------
// Recurrent kernel: one CTA per batch, 384 threads, loop over T.
// a_hh resident in smem for the whole kernel; w_hh_w / w_hh_c streamed
// through smem in 16-row chunks via cp.async (double buffered).
// ---------------------------------------------------------------------
struct alignas(16) RecSmem {
    float ahh[Hn][Hn];        // 64KB, persistent
    float wsw[2][16][K3];     // 48KB staging (whhw)
    float wsc[2][16][K3];     // 48KB staging (whhc)
    float hx[Xn][Hn];
    float cx[Xn][Hn];
    float h0[Hn];
    float gws[9][K3];
    float c1s[Xn][Hn];
    float alphas[Xn][Hn];
    float ig[Hn], og[Hn], gg[Hn];
    int   js[Xn];
};

__global__ __launch_bounds__(384, 1) void lattice_recurrent(
    const float* __restrict__ whhw,   // [128,384]
    const float* __restrict__ whhc,   // [128,384]
    const float* __restrict__ ahh,    // [128,128]
    const int*   __restrict__ srcp,   // [B,T,X]
    const int*   __restrict__ cntp,   // [B,T]
    float* __restrict__ out)          // hs then cs, each [B,T,H]
{
    extern __shared__ unsigned char smem_raw[];
    RecSmem& sm = *reinterpret_cast<RecSmem*>(smem_raw);

    const int b   = blockIdx.x;
    const int tid = threadIdx.x;
    const int col = tid;  // 0..383

    float* hs = out;
    float* cs = out + (size_t)Bn * Tn * Hn;

    // ---- stage a_hh into smem once ----
    for (int i = tid; i < Hn * Hn / 4; i += 384)
        ((float4*)sm.ahh)[i] = ((const float4*)ahh)[i];

    // per-thread cp.async unit mapping (8 x 16B per chunk: 4 for each matrix)
    int crow[4], ccol[4];
#pragma unroll
    for (int i = 0; i < 4; i++) {
        const int u = tid + i * 384;       // 0..1535
        crow[i] = u / 96;                  // 0..15 (k row within chunk)
        ccol[i] = (u % 96) * 4;            // 0..380 (col)
    }
    const uint32_t wbase[2] = {
        (uint32_t)__cvta_generic_to_shared(&sm.wsw[0][0][0]),
        (uint32_t)__cvta_generic_to_shared(&sm.wsw[1][0][0])
    };
    const uint32_t cbase[2] = {
        (uint32_t)__cvta_generic_to_shared(&sm.wsc[0][0][0]),
        (uint32_t)__cvta_generic_to_shared(&sm.wsc[1][0][0])
    };
    __syncthreads();

    for (int t = 0; t < Tn; t++) {
        if (tid < Xn) sm.js[tid] = srcp[(b * Tn + t) * Xn + tid];

        // issue weight chunks 0 and 1 (independent of step data)
#pragma unroll
        for (int c0 = 0; c0 < 2; c0++) {
            const int kc = c0 << 4;
#pragma unroll
            for (int i = 0; i < 4; i++)
                cpa16(wbase[c0] + (uint32_t)((crow[i] * K3 + ccol[i]) << 2),
                      whhw + (size_t)(kc + crow[i]) * K3 + ccol[i]);
#pragma unroll
            for (int i = 0; i < 4; i++)
                cpa16(cbase[c0] + (uint32_t)((crow[i] * K3 + ccol[i]) << 2),
                      whhc + (size_t)(kc + crow[i]) * K3 + ccol[i]);
            cp_commit();
        }
        __syncthreads();   // js visible

        // ---- phase 0: gather history (hx/cx as float4) + h0 ----
        for (int u = tid; u < 512; u += 384) {
            const int row  = u >> 5;          // 0..15
            const int lane = (u & 31) << 2;   // float offset
            const int x = row & 7;
            const float* srcb = (row < 8) ? hs : cs;
            float4 v = *(const float4*)(srcb + ((size_t)b * Tn + sm.js[x]) * Hn + lane);
            float* dst = (row < 8) ? &sm.hx[x][lane] : &sm.cx[x][lane];
            *(float4*)dst = v;
        }
        if (tid < 32) {
            float4 v = make_float4(0.f, 0.f, 0.f, 0.f);
            if (t > 0) v = *(const float4*)(hs + ((size_t)b * Tn + (t - 1)) * Hn + tid * 4);
            *(float4*)&sm.h0[tid * 4] = v;
        }

        // ---- acc init from precomputed input projections ----
        float acc[9];
        {
            const float* pw = g_Pw + ((size_t)(b * Tn + t) * Xn) * K3 + col;
#pragma unroll
            for (int x = 0; x < 8; x++) acc[x] = pw[x * K3];
            acc[8] = g_Pc[(size_t)(b * Tn + t) * K3 + col];
        }
        __syncthreads();   // gather visible

        // ---- phase 1: chunked hidden-state matmul ----
        for (int c = 0; c < 8; c++) {
            if (c < 7) cp_wait<1>(); else cp_wait<0>();
            __syncthreads();  // chunk c visible to all

            const int bi = c & 1;
            const int kc = c << 4;
            const float (*ww)[K3] = sm.wsw[bi];
            const float (*wc)[K3] = sm.wsc[bi];
#pragma unroll
            for (int q = 0; q < 4; q++) {
                float4 h0v = *(const float4*)(sm.h0 + kc + q * 4);
                float4 hv[8];
#pragma unroll
                for (int x = 0; x < 8; x++)
                    hv[x] = *(const float4*)(&sm.hx[x][kc + q * 4]);
#pragma unroll
                for (int j = 0; j < 4; j++) {
                    const float wv  = ww[q * 4 + j][col];
                    const float wcv = wc[q * 4 + j][col];
#pragma unroll
                    for (int x = 0; x < 8; x++)
                        acc[x] = fmaf(((const float*)&hv[x])[j], wv, acc[x]);
                    acc[8] = fmaf(((const float*)&h0v)[j], wcv, acc[8]);
                }
            }

            if (c < 6) {
                __syncthreads();  // everyone done reading buf (c&1)
                const int cn2 = c + 2;
                const int kc2 = cn2 << 4;
                const int bi2 = cn2 & 1;
#pragma unroll
                for (int i = 0; i < 4; i++)
                    cpa16(wbase[bi2] + (uint32_t)((crow[i] * K3 + ccol[i]) << 2),
                          whhw + (size_t)(kc2 + crow[i]) * K3 + ccol[i]);
#pragma unroll
                for (int i = 0; i < 4; i++)
                    cpa16(cbase[bi2] + (uint32_t)((crow[i] * K3 + ccol[i]) << 2),
                          whhc + (size_t)(kc2 + crow[i]) * K3 + ccol[i]);
                cp_commit();
            }
        }
#pragma unroll
        for (int r = 0; r < 9; r++) sm.gws[r][col] = acc[r];
        __syncthreads();

        // ---- phase 2: gates -> c1_skip ----
        if (tid < Hn) {
            sm.ig[tid] = sigm(sm.gws[8][tid]);
            sm.og[tid] = sigm(sm.gws[8][tid + 128]);
            sm.gg[tid] = tanhf(sm.gws[8][tid + 256]);
        }
        for (int i = tid; i < Xn * Hn; i += 384) {
            const int x = i >> 7, h = i & 127;
            const float fg = sigm(sm.gws[x][h]);
            const float iw = sigm(sm.gws[x][h + 128]);
            const float gv = tanhf(sm.gws[x][h + 256]);
            sm.c1s[x][h] = fg * sm.cx[x][h] + iw * gv;
        }
        __syncthreads();

        // ---- phase 3: alpha = sigmoid(P_a + c1_skip @ a_hh) ----
        if (tid < 256) {
            const int x  = tid >> 5;
            const int h4 = (tid & 31) << 2;
            float4 av = *(const float4*)(g_Pa + (size_t)(b * Tn + t) * Hn + h4);
            float a0 = av.x, a1 = av.y, a2 = av.z, a3 = av.w;
#pragma unroll 8
            for (int k4 = 0; k4 < 32; k4++) {
                float4 cv = *(const float4*)&sm.c1s[x][k4 << 2];
#pragma unroll
                for (int j = 0; j < 4; j++) {
                    const float cj = ((const float*)&cv)[j];
                    float4 wv = *(const float4*)&sm.ahh[(k4 << 2) + j][h4];
                    a0 = fmaf(cj, wv.x, a0);
                    a1 = fmaf(cj, wv.y, a1);
                    a2 = fmaf(cj, wv.z, a2);
                    a3 = fmaf(cj, wv.w, a3);
                }
            }
            sm.alphas[x][h4 + 0] = sigm(a0);
            sm.alphas[x][h4 + 1] = sigm(a1);
            sm.alphas[x][h4 + 2] = sigm(a2);
            sm.alphas[x][h4 + 3] = sigm(a3);
        }
        __syncthreads();

        // ---- phase 4: masked softmax merge, write h1/c1 ----
        if (tid < Hn) {
            const int h  = tid;
            const int cn = cntp[b * Tn + t];
            const float e0 = expf(sm.ig[h]);
            float den = e0;
            float num = sm.gg[h] * e0;
#pragma unroll
            for (int x = 0; x < 8; x++) {
                if (x < cn) {
                    const float ea = expf(sm.alphas[x][h]);
                    den += ea;
                    num += sm.c1s[x][h] * ea;
                }
            }
            const float c1 = num / den;
            hs[((size_t)b * Tn + t) * Hn + h] = sm.og[h] * tanhf(c1);
            cs[((size_t)b * Tn + t) * Hn + h] = c1;
        }
        __syncthreads();
    }
}

// ---------------------------------------------------------------------
extern "C" void kernel_launch(void* const* d_in, const int* in_sizes, int n_in,
                              void* d_out, int out_size)
{
    int i_src, i_cnt, i_wihc, i_whhc, i_bc, i_aih, i_ahh, i_ab, i_wihw, i_whhw, i_bw;
    if (in_sizes[2] == Bn) {
        i_src = 3;  i_cnt = 4;
        i_wihc = 5; i_whhc = 6; i_bc = 7;
        i_aih = 8;  i_ahh = 9;  i_ab = 10;
        i_wihw = 11; i_whhw = 12; i_bw = 13;
    } else {
        i_wihc = 2; i_whhc = 3; i_bc = 4;
        i_aih = 5;  i_ahh = 6;  i_ab = 7;
        i_wihw = 8; i_whhw = 9; i_bw = 10;
        i_src = 12; i_cnt = 13;
    }

    const float* inp        = (const float*)d_in[0];
    const float* skip_words = (const float*)d_in[1];
    const int*   srcp       = (const int*)d_in[i_src];
    const int*   cntp       = (const int*)d_in[i_cnt];
    const float* wihc = (const float*)d_in[i_wihc];
    const float* whhc = (const float*)d_in[i_whhc];
    const float* bc   = (const float*)d_in[i_bc];
    const float* aih  = (const float*)d_in[i_aih];
    const float* ahh  = (const float*)d_in[i_ahh];
    const float* ab   = (const float*)d_in[i_ab];
    const float* wihw = (const float*)d_in[i_wihw];
    const float* whhw = (const float*)d_in[i_whhw];
    const float* bw   = (const float*)d_in[i_bw];

    float *Pw, *Pc, *Pa;
    cudaGetSymbolAddress((void**)&Pw, g_Pw);
    cudaGetSymbolAddress((void**)&Pc, g_Pc);
    cudaGetSymbolAddress((void**)&Pa, g_Pa);

    // Precompute input projections
    gemm128<<<dim3(K3 / 128, (Bn * Tn * Xn) / 128), 256>>>(skip_words, wihw, bw, Pw, K3);
    gemm128<<<dim3(K3 / 128, (Bn * Tn) / 128),      256>>>(inp,        wihc, bc, Pc, K3);
    gemm128<<<dim3(Hn / 128, (Bn * Tn) / 128),      256>>>(inp,        aih,  ab, Pa, Hn);

    // Recurrent scan with large dynamic smem
    static int attr_done = 0;
    if (!attr_done) {
        cudaFuncSetAttribute(lattice_recurrent,
                             cudaFuncAttributeMaxDynamicSharedMemorySize,
                             (int)sizeof(RecSmem));
        attr_done = 1;
    }
    lattice_recurrent<<<Bn, 384, sizeof(RecSmem)>>>(whhw, whhc, ahh, srcp, cntp,
                                                    (float*)d_out);
}

// round 4
// speedup vs baseline: 2.3590x; 1.4157x over previous
#include <cuda_runtime.h>
#include <math.h>
#include <stdint.h>

#define Bn 64
#define Tn 512
#define Xn 8
#define Hn 128
#define K3 384   // 3*H
#define W2 768   // combined [whhw | whhc] columns (interleaved pairs)

// -------- device scratch (allocation-free, zero-initialized at load) --------
__device__ float g_Pw[(size_t)Bn * Tn * Xn * K3];  // [B,T,X,3H]
__device__ float g_Pc[(size_t)Bn * Tn * K3];       // [B,T,3H]
__device__ float g_Pa[(size_t)Bn * Tn * Hn];       // [B,T,H]
__device__ float g_proj[(size_t)Bn * Tn * K3];     // proj[b][s] = h1(s) @ w_hh_w
__device__ float g_Wcomb[128 * W2];                // [k][2c]=whhw[k][c], [2c+1]=whhc[k][c]

// -------- asm helpers --------
__device__ __forceinline__ void cpa16(uint32_t s, const void* g) {
    asm volatile("cp.async.cg.shared.global [%0], [%1], 16;" :: "r"(s), "l"(g));
}
__device__ __forceinline__ void cp_commit() { asm volatile("cp.async.commit_group;"); }
template<int N> __device__ __forceinline__ void cp_wait() {
    asm volatile("cp.async.wait_group %0;" :: "n"(N));
}
__device__ __forceinline__ unsigned long long pk2(float x, float y) {
    unsigned long long r;
    asm("mov.b64 %0, {%1, %2};" : "=l"(r) : "f"(x), "f"(y));
    return r;
}
__device__ __forceinline__ void upk2(unsigned long long v, float& x, float& y) {
    asm("mov.b64 {%0, %1}, %2;" : "=f"(x), "=f"(y) : "l"(v));
}
__device__ __forceinline__ unsigned long long fma2(
    unsigned long long a, unsigned long long b, unsigned long long c) {
    unsigned long long d;
    asm("fma.rn.f32x2 %0, %1, %2, %3;" : "=l"(d) : "l"(a), "l"(b), "l"(c));
    return d;
}

__device__ __forceinline__ float sigm(float x) { return 1.f / (1.f + __expf(-x)); }
__device__ __forceinline__ float tanh_(float x) {
    float e = __expf(2.f * x);
    return 1.f - 2.f / (e + 1.f);
}

// ---------------------------------------------------------------------
// Build combined interleaved weight matrix for the recurrent matvec.
// ---------------------------------------------------------------------
__global__ void build_wcomb(const float* __restrict__ whhw,
                            const float* __restrict__ whhc) {
    int i = blockIdx.x * blockDim.x + threadIdx.x;  // 0 .. 128*384-1
    if (i >= 128 * K3) return;
    int k = i / K3, c = i % K3;
    g_Wcomb[k * W2 + 2 * c]     = whhw[k * K3 + c];
    g_Wcomb[k * W2 + 2 * c + 1] = whhc[k * K3 + c];
}

// ---------------------------------------------------------------------
// SGEMM with fma.rn.f32x2: C[M,128] x W[128,N] + bias.  128x128 tile,
// BK=8, 256 threads, 8x8 microtile, double-buffered smem.
// ---------------------------------------------------------------------
__global__ __launch_bounds__(256) void gemm128(
    const float* __restrict__ A, const float* __restrict__ W,
    const float* __restrict__ bias, float* __restrict__ C, int N)
{
    __shared__ float As[2][8][128];
    __shared__ float Bs[2][8][128];

    const int tid = threadIdx.x;
    const int m0 = blockIdx.y * 128;
    const int n0 = blockIdx.x * 128;

    const int arow = tid >> 1;
    const int ak4  = (tid & 1) << 2;
    const int brow = tid >> 5;
    const int bc4  = (tid & 31) << 2;
    const int ty   = tid >> 4;
    const int tx   = tid & 15;

    const float* Ag = A + (size_t)(m0 + arow) * 128 + ak4;
    const float* Wg = W + (size_t)brow * N + n0 + bc4;

    unsigned long long acc2[8][4];
#pragma unroll
    for (int i = 0; i < 8; i++)
#pragma unroll
        for (int j = 0; j < 4; j++) acc2[i][j] = 0ull;

    float4 ra = *(const float4*)Ag;
    float4 rb = *(const float4*)Wg;
    As[0][ak4 + 0][arow] = ra.x; As[0][ak4 + 1][arow] = ra.y;
    As[0][ak4 + 2][arow] = ra.z; As[0][ak4 + 3][arow] = ra.w;
    *(float4*)&Bs[0][brow][bc4] = rb;
    __syncthreads();

    int p = 0;
    for (int kc = 8; kc <= 128; kc += 8) {
        const bool more = (kc < 128);
        if (more) {
            ra = *(const float4*)(Ag + kc);
            rb = *(const float4*)(Wg + (size_t)kc * N);
        }
#pragma unroll
        for (int k = 0; k < 8; k++) {
            float af[8], bf[8];
            *(float4*)&af[0] = *(const float4*)&As[p][k][ty * 4];
            *(float4*)&af[4] = *(const float4*)&As[p][k][ty * 4 + 64];
            *(float4*)&bf[0] = *(const float4*)&Bs[p][k][tx * 4];
            *(float4*)&bf[4] = *(const float4*)&Bs[p][k][tx * 4 + 64];
            unsigned long long bd[4];
            bd[0] = pk2(bf[0], bf[1]); bd[1] = pk2(bf[2], bf[3]);
            bd[2] = pk2(bf[4], bf[5]); bd[3] = pk2(bf[6], bf[7]);
#pragma unroll
            for (int i = 0; i < 8; i++) {
                unsigned long long ad = pk2(af[i], af[i]);
#pragma unroll
                for (int j = 0; j < 4; j++) acc2[i][j] = fma2(ad, bd[j], acc2[i][j]);
            }
        }
        if (more) {
            p ^= 1;
            As[p][ak4 + 0][arow] = ra.x; As[p][ak4 + 1][arow] = ra.y;
            As[p][ak4 + 2][arow] = ra.z; As[p][ak4 + 3][arow] = ra.w;
            *(float4*)&Bs[p][brow][bc4] = rb;
            __syncthreads();
        }
    }

    float bv[8];
#pragma unroll
    for (int j = 0; j < 4; j++) {
        bv[j]     = bias[n0 + tx * 4 + j];
        bv[j + 4] = bias[n0 + tx * 4 + 64 + j];
    }
#pragma unroll
    for (int i = 0; i < 8; i++) {
        const int r = m0 + ty * 4 + (i & 3) + ((i >> 2) << 6);
        float a0, a1, a2, a3, a4, a5, a6, a7;
        upk2(acc2[i][0], a0, a1); upk2(acc2[i][1], a2, a3);
        upk2(acc2[i][2], a4, a5); upk2(acc2[i][3], a6, a7);
        float4 o0, o1;
        o0.x = a0 + bv[0]; o0.y = a1 + bv[1]; o0.z = a2 + bv[2]; o0.w = a3 + bv[3];
        o1.x = a4 + bv[4]; o1.y = a5 + bv[5]; o1.z = a6 + bv[6]; o1.w = a7 + bv[7];
        *(float4*)&C[(size_t)r * N + n0 + tx * 4]      = o0;
        *(float4*)&C[(size_t)r * N + n0 + tx * 4 + 64] = o1;
    }
}

// ---------------------------------------------------------------------
// Recurrent scan with projection caching. One CTA per batch, 384 thr.
// ---------------------------------------------------------------------
struct alignas(16) RecSmem {
    float wbuf[3][16][W2];   // 147456 B, triple-buffered weight chunks
    float c1s[Xn][Hn];       // 4096
    float alphas[Xn][Hn];    // 4096
    float projw[K3];         // 1536
    float gc[K3];            // 1536
    float ig[Hn], og[Hn], gg[Hn];  // 1536
    float h1[Hn];            // 512
    int   js[Xn];
    int   cn;
};

__global__ __launch_bounds__(384, 1) void lattice_recurrent(
    const float* __restrict__ ahh,    // [128,128]
    const int*   __restrict__ srcp,   // [B,T,X]
    const int*   __restrict__ cntp,   // [B,T]
    float* __restrict__ out)          // hs then cs, each [B,T,H]
{
    extern __shared__ unsigned char smem_raw[];
    RecSmem& sm = *reinterpret_cast<RecSmem*>(smem_raw);

    const int b    = blockIdx.x;
    const int tid  = threadIdx.x;
    const int wid  = tid >> 5;
    const int lane = tid & 31;
    const int col  = tid;              // 0..383

    float* hs = out;
    float* cs = out + (size_t)Bn * Tn * Hn;
    const float* Wc = g_Wcomb;
    const ulonglong2* ahh2 = (const ulonglong2*)ahh;

    uint32_t wb[3];
#pragma unroll
    for (int i = 0; i < 3; i++)
        wb[i] = (uint32_t)__cvta_generic_to_shared(&sm.wbuf[i][0][0]);

    for (int t = 0; t < Tn; t++) {
        if (tid < Xn)   sm.js[tid] = srcp[(b * Tn + t) * Xn + tid];
        if (tid == 32)  sm.cn = cntp[b * Tn + t];

        // ---- phase A: combined matvec h1(t-1) @ [whhw | whhc] ----
        if (t > 0) {
            // issue chunks 0,1
#pragma unroll
            for (int c0 = 0; c0 < 2; c0++) {
                const float* src = Wc + (size_t)c0 * 16 * W2;
#pragma unroll
                for (int i = 0; i < 8; i++) {
                    int u = tid + i * 384;
                    cpa16(wb[c0] + (uint32_t)(u * 16), src + u * 4);
                }
                cp_commit();
            }

            float accw = 0.f, accc = 0.f;
            for (int c = 0; c < 8; c++) {
                if (c < 7) cp_wait<1>(); else cp_wait<0>();
                __syncthreads();   // chunk c visible; buf[(c+2)%3] free

                if (c < 6) {
                    const int cn2 = c + 2;
                    const float* src = Wc + (size_t)cn2 * 16 * W2;
#pragma unroll
                    for (int i = 0; i < 8; i++) {
                        int u = tid + i * 384;
                        cpa16(wb[cn2 % 3] + (uint32_t)(u * 16), src + u * 4);
                    }
                    cp_commit();
                }

                const float* wbp = &sm.wbuf[c % 3][0][0];
#pragma unroll
                for (int q = 0; q < 4; q++) {
                    float4 hv = *(const float4*)&sm.h1[c * 16 + q * 4];
                    const float* hvf = (const float*)&hv;
#pragma unroll
                    for (int j = 0; j < 4; j++) {
                        float2 w = *(const float2*)(wbp + (q * 4 + j) * W2 + 2 * col);
                        accw = fmaf(hvf[j], w.x, accw);
                        accc = fmaf(hvf[j], w.y, accc);
                    }
                }
            }
            sm.projw[col] = accw;
            g_proj[((size_t)b * Tn + (t - 1)) * K3 + col] = accw;
            sm.gc[col] = accc + g_Pc[(size_t)(b * Tn + t) * K3 + col];
        } else {
            sm.gc[col] = g_Pc[(size_t)(b * Tn + t) * K3 + col];
        }
        __syncthreads();   // projw/gc/js/cn visible

        const int cn = sm.cn;

        // ---- phase B: gates (threads 256..383) + c1_skip (warps 0..7) ----
        if (tid >= 256) {
            const int h = tid - 256;
            sm.ig[h] = sigm(sm.gc[h]);
            sm.og[h] = sigm(sm.gc[h + 128]);
            sm.gg[h] = tanh_(sm.gc[h + 256]);
        } else if (wid < 8 && wid < cn) {
            const int x = wid;
            const int s = sm.js[x];
            const float* pr = (t > 0 && s == t - 1)
                              ? sm.projw
                              : (g_proj + ((size_t)b * Tn + s) * K3);
            const int h4 = lane * 4;
            float4 g0 = *(const float4*)(pr + h4);
            float4 g1 = *(const float4*)(pr + 128 + h4);
            float4 g2 = *(const float4*)(pr + 256 + h4);
            const float* pw = g_Pw + ((size_t)(b * Tn + t) * Xn + x) * K3;
            float4 p0 = *(const float4*)(pw + h4);
            float4 p1 = *(const float4*)(pw + 128 + h4);
            float4 p2 = *(const float4*)(pw + 256 + h4);
            float4 cx = *(const float4*)(cs + ((size_t)b * Tn + s) * Hn + h4);
            const float* g0f = (const float*)&g0; const float* g1f = (const float*)&g1;
            const float* g2f = (const float*)&g2; const float* p0f = (const float*)&p0;
            const float* p1f = (const float*)&p1; const float* p2f = (const float*)&p2;
            const float* cxf = (const float*)&cx;
#pragma unroll
            for (int j = 0; j < 4; j++) {
                const float fg = sigm(g0f[j] + p0f[j]);
                const float iw = sigm(g1f[j] + p1f[j]);
                const float gv = tanh_(g2f[j] + p2f[j]);
                sm.c1s[x][h4 + j] = fg * cxf[j] + iw * gv;
            }
        }
        __syncthreads();

        // ---- phase E: alpha = sigmoid(P_a + c1_skip @ a_hh), fma.f32x2 ----
        if (wid < 8 && wid < cn) {
            const int x  = wid;
            const int h4 = lane * 4;
            float4 pa = *(const float4*)(g_Pa + (size_t)(b * Tn + t) * Hn + h4);
            unsigned long long a01 = pk2(pa.x, pa.y);
            unsigned long long a23 = pk2(pa.z, pa.w);
#pragma unroll 8
            for (int k4 = 0; k4 < 32; k4++) {
                float4 cv = *(const float4*)&sm.c1s[x][k4 << 2];
                const float* cvf = (const float*)&cv;
#pragma unroll
                for (int j = 0; j < 4; j++) {
                    unsigned long long cd = pk2(cvf[j], cvf[j]);
                    ulonglong2 wv = ahh2[(size_t)((k4 << 2) + j) * 32 + lane];
                    a01 = fma2(cd, wv.x, a01);
                    a23 = fma2(cd, wv.y, a23);
                }
            }
            float r0, r1, r2, r3;
            upk2(a01, r0, r1); upk2(a23, r2, r3);
            sm.alphas[x][h4 + 0] = sigm(r0);
            sm.alphas[x][h4 + 1] = sigm(r1);
            sm.alphas[x][h4 + 2] = sigm(r2);
            sm.alphas[x][h4 + 3] = sigm(r3);
        }
        __syncthreads();

        // ---- phase F: masked softmax merge, write h1/c1 ----
        if (tid < Hn) {
            const int h = tid;
            const float e0 = __expf(sm.ig[h]);
            float den = e0;
            float num = sm.gg[h] * e0;
#pragma unroll
            for (int x = 0; x < 8; x++) {
                if (x < cn) {
                    const float ea = __expf(sm.alphas[x][h]);
                    den += ea;
                    num += sm.c1s[x][h] * ea;
                }
            }
            const float c1 = num / den;
            const float h1v = sm.og[h] * tanh_(c1);
            hs[((size_t)b * Tn + t) * Hn + h] = h1v;
            cs[((size_t)b * Tn + t) * Hn + h] = c1;
            sm.h1[h] = h1v;
        }
        __syncthreads();
    }
}

// ---------------------------------------------------------------------
extern "C" void kernel_launch(void* const* d_in, const int* in_sizes, int n_in,
                              void* d_out, int out_size)
{
    int i_src, i_cnt, i_wihc, i_whhc, i_bc, i_aih, i_ahh, i_ab, i_wihw, i_whhw, i_bw;
    if (in_sizes[2] == Bn) {
        i_src = 3;  i_cnt = 4;
        i_wihc = 5; i_whhc = 6; i_bc = 7;
        i_aih = 8;  i_ahh = 9;  i_ab = 10;
        i_wihw = 11; i_whhw = 12; i_bw = 13;
    } else {
        i_wihc = 2; i_whhc = 3; i_bc = 4;
        i_aih = 5;  i_ahh = 6;  i_ab = 7;
        i_wihw = 8; i_whhw = 9; i_bw = 10;
        i_src = 12; i_cnt = 13;
    }

    const float* inp        = (const float*)d_in[0];
    const float* skip_words = (const float*)d_in[1];
    const int*   srcp       = (const int*)d_in[i_src];
    const int*   cntp       = (const int*)d_in[i_cnt];
    const float* wihc = (const float*)d_in[i_wihc];
    const float* whhc = (const float*)d_in[i_whhc];
    const float* bc   = (const float*)d_in[i_bc];
    const float* aih  = (const float*)d_in[i_aih];
    const float* ahh  = (const float*)d_in[i_ahh];
    const float* ab   = (const float*)d_in[i_ab];
    const float* wihw = (const float*)d_in[i_wihw];
    const float* whhw = (const float*)d_in[i_whhw];
    const float* bw   = (const float*)d_in[i_bw];

    float *Pw, *Pc, *Pa;
    cudaGetSymbolAddress((void**)&Pw, g_Pw);
    cudaGetSymbolAddress((void**)&Pc, g_Pc);
    cudaGetSymbolAddress((void**)&Pa, g_Pa);

    // Combined recurrent weight matrix (interleaved pairs)
    build_wcomb<<<(128 * K3 + 511) / 512, 512>>>(whhw, whhc);

    // Input projections
    gemm128<<<dim3(K3 / 128, (Bn * Tn * Xn) / 128), 256>>>(skip_words, wihw, bw, Pw, K3);
    gemm128<<<dim3(K3 / 128, (Bn * Tn) / 128),      256>>>(inp,        wihc, bc, Pc, K3);
    gemm128<<<dim3(Hn / 128, (Bn * Tn) / 128),      256>>>(inp,        aih,  ab, Pa, Hn);

    static int attr_done = 0;
    if (!attr_done) {
        cudaFuncSetAttribute(lattice_recurrent,
                             cudaFuncAttributeMaxDynamicSharedMemorySize,
                             (int)sizeof(RecSmem));
        attr_done = 1;
    }
    lattice_recurrent<<<Bn, 384, sizeof(RecSmem)>>>(ahh, srcp, cntp, (float*)d_out);
}

// round 6
// speedup vs baseline: 4.0087x; 1.6993x over previous
#include <cuda_runtime.h>
#include <math.h>
#include <stdint.h>

#define Bn 64
#define Tn 512
#define Xn 8
#define Hn 128
#define K3 384   // 3*H
#define HB 64    // half of H

// -------- device scratch (allocation-free) --------
__device__ float g_Pw[(size_t)Bn * Tn * Xn * K3];  // [B,T,X,3H]
__device__ float g_Pc[(size_t)Bn * Tn * K3];       // [B,T,3H]
__device__ float g_Pa[(size_t)Bn * Tn * Hn];       // [B,T,H]
__device__ float g_proj[(size_t)Bn * Tn * K3];     // proj[b][s] = h1(s) @ w_hh_w

// -------- asm helpers --------
__device__ __forceinline__ unsigned long long pk2(float x, float y) {
    unsigned long long r;
    asm("mov.b64 %0, {%1, %2};" : "=l"(r) : "f"(x), "f"(y));
    return r;
}
__device__ __forceinline__ void upk2(unsigned long long v, float& x, float& y) {
    asm("mov.b64 {%0, %1}, %2;" : "=f"(x), "=f"(y) : "l"(v));
}
__device__ __forceinline__ unsigned long long fma2(
    unsigned long long a, unsigned long long b, unsigned long long c) {
    unsigned long long d;
    asm("fma.rn.f32x2 %0, %1, %2, %3;" : "=l"(d) : "l"(a), "l"(b), "l"(c));
    return d;
}
__device__ __forceinline__ uint32_t smem_u32(const void* p) {
    return (uint32_t)__cvta_generic_to_shared(p);
}
__device__ __forceinline__ uint32_t mapa_u32(uint32_t a, uint32_t rank) {
    uint32_t d;
    asm("mapa.shared::cluster.u32 %0, %1, %2;" : "=r"(d) : "r"(a), "r"(rank));
    return d;
}
__device__ __forceinline__ void st_cluster_f2(uint32_t a, float x, float y) {
    asm volatile("st.shared::cluster.v2.f32 [%0], {%1, %2};"
                 :: "r"(a), "f"(x), "f"(y) : "memory");
}
#define CLUSTER_ARRIVE() asm volatile("barrier.cluster.arrive.aligned;" ::: "memory")
#define CLUSTER_WAIT()   asm volatile("barrier.cluster.wait.aligned;"   ::: "memory")

__device__ __forceinline__ float sigm(float x) { return 1.f / (1.f + __expf(-x)); }
__device__ __forceinline__ float tanh_(float x) {
    float e = __expf(2.f * x);
    return 1.f - 2.f / (e + 1.f);
}

// ---------------------------------------------------------------------
// SGEMM with fma.rn.f32x2 (unchanged from round 4)
// ---------------------------------------------------------------------
__global__ __launch_bounds__(256) void gemm128(
    const float* __restrict__ A, const float* __restrict__ W,
    const float* __restrict__ bias, float* __restrict__ C, int N)
{
    __shared__ float As[2][8][128];
    __shared__ float Bs[2][8][128];

    const int tid = threadIdx.x;
    const int m0 = blockIdx.y * 128;
    const int n0 = blockIdx.x * 128;

    const int arow = tid >> 1;
    const int ak4  = (tid & 1) << 2;
    const int brow = tid >> 5;
    const int bc4  = (tid & 31) << 2;
    const int ty   = tid >> 4;
    const int tx   = tid & 15;

    const float* Ag = A + (size_t)(m0 + arow) * 128 + ak4;
    const float* Wg = W + (size_t)brow * N + n0 + bc4;

    unsigned long long acc2[8][4];
#pragma unroll
    for (int i = 0; i < 8; i++)
#pragma unroll
        for (int j = 0; j < 4; j++) acc2[i][j] = 0ull;

    float4 ra = *(const float4*)Ag;
    float4 rb = *(const float4*)Wg;
    As[0][ak4 + 0][arow] = ra.x; As[0][ak4 + 1][arow] = ra.y;
    As[0][ak4 + 2][arow] = ra.z; As[0][ak4 + 3][arow] = ra.w;
    *(float4*)&Bs[0][brow][bc4] = rb;
    __syncthreads();

    int p = 0;
    for (int kc = 8; kc <= 128; kc += 8) {
        const bool more = (kc < 128);
        if (more) {
            ra = *(const float4*)(Ag + kc);
            rb = *(const float4*)(Wg + (size_t)kc * N);
        }
#pragma unroll
        for (int k = 0; k < 8; k++) {
            float af[8], bf[8];
            *(float4*)&af[0] = *(const float4*)&As[p][k][ty * 4];
            *(float4*)&af[4] = *(const float4*)&As[p][k][ty * 4 + 64];
            *(float4*)&bf[0] = *(const float4*)&Bs[p][k][tx * 4];
            *(float4*)&bf[4] = *(const float4*)&Bs[p][k][tx * 4 + 64];
            unsigned long long bd[4];
            bd[0] = pk2(bf[0], bf[1]); bd[1] = pk2(bf[2], bf[3]);
            bd[2] = pk2(bf[4], bf[5]); bd[3] = pk2(bf[6], bf[7]);
#pragma unroll
            for (int i = 0; i < 8; i++) {
                unsigned long long ad = pk2(af[i], af[i]);
#pragma unroll
                for (int j = 0; j < 4; j++) acc2[i][j] = fma2(ad, bd[j], acc2[i][j]);
            }
        }
        if (more) {
            p ^= 1;
            As[p][ak4 + 0][arow] = ra.x; As[p][ak4 + 1][arow] = ra.y;
            As[p][ak4 + 2][arow] = ra.z; As[p][ak4 + 3][arow] = ra.w;
            *(float4*)&Bs[p][brow][bc4] = rb;
            __syncthreads();
        }
    }

    float bv[8];
#pragma unroll
    for (int j = 0; j < 4; j++) {
        bv[j]     = bias[n0 + tx * 4 + j];
        bv[j + 4] = bias[n0 + tx * 4 + 64 + j];
    }
#pragma unroll
    for (int i = 0; i < 8; i++) {
        const int r = m0 + ty * 4 + (i & 3) + ((i >> 2) << 6);
        float a0, a1, a2, a3, a4, a5, a6, a7;
        upk2(acc2[i][0], a0, a1); upk2(acc2[i][1], a2, a3);
        upk2(acc2[i][2], a4, a5); upk2(acc2[i][3], a6, a7);
        float4 o0, o1;
        o0.x = a0 + bv[0]; o0.y = a1 + bv[1]; o0.z = a2 + bv[2]; o0.w = a3 + bv[3];
        o1.x = a4 + bv[4]; o1.y = a5 + bv[5]; o1.z = a6 + bv[6]; o1.w = a7 + bv[7];
        *(float4*)&C[(size_t)r * N + n0 + tx * 4]      = o0;
        *(float4*)&C[(size_t)r * N + n0 + tx * 4 + 64] = o1;
    }
}

// ---------------------------------------------------------------------
// Recurrent scan: 2-CTA cluster per batch, weights fully resident.
// ---------------------------------------------------------------------
struct alignas(16) RecSmem {
    float whhw_hi[32][K3];   // 49152 B : whhw rows k0+32..k0+63
    float ahh[Hn][HB];       // 32768 B : a_hh[:, rank*64 .. +64)
    float2 pmv[K3];          //  3072 B : peer matvec partial (projw, gc)
    float projw[K3];         //  1536 B
    float gc[K3];            //  1536 B
    float c1s[Xn][Hn];       //  4096 B : own half local, peer half via DSMEM
    float alphas[Xn][HB];    //  2048 B
    float ig[HB], og[HB], gg[HB];  // 768 B
    float h1[HB];            //   256 B : own h-half of h1(t)
    int   js[Xn];
    int   cn;
};

__global__ __launch_bounds__(384, 1) __cluster_dims__(2, 1, 1)
void lattice_recurrent(
    const float* __restrict__ whhw,   // [128,384]
    const float* __restrict__ whhc,   // [128,384]
    const float* __restrict__ ahh_g,  // [128,128]
    const int*   __restrict__ srcp,   // [B,T,X]
    const int*   __restrict__ cntp,   // [B,T]
    float* __restrict__ out)          // hs then cs, each [B,T,H]
{
    extern __shared__ unsigned char smem_raw[];
    RecSmem& sm = *reinterpret_cast<RecSmem*>(smem_raw);

    const int rank = blockIdx.x & 1;          // cluster rank
    const int b    = blockIdx.x >> 1;         // batch
    const int peer = rank ^ 1;
    const int tid  = threadIdx.x;
    const int col  = tid;                     // 0..383 output column
    const int k0   = rank * HB;               // own k/h half base

    float* hs = out;
    float* cs = out + (size_t)Bn * Tn * Hn;

    // ---- one-time init: weights into regs + smem ----
    float wc_r[64];   // whhc[k0+k][col]
    float ww_r[32];   // whhw[k0+k][col], k<32
#pragma unroll
    for (int k = 0; k < 64; k++) wc_r[k] = whhc[(size_t)(k0 + k) * K3 + col];
#pragma unroll
    for (int k = 0; k < 32; k++) ww_r[k] = whhw[(size_t)(k0 + k) * K3 + col];
    for (int i = tid; i < 32 * K3; i += 384) {
        int r = i / K3, c = i % K3;
        sm.whhw_hi[r][c] = whhw[(size_t)(k0 + 32 + r) * K3 + c];
    }
    for (int i = tid; i < Hn * HB; i += 384) {
        int k = i / HB, j = i % HB;
        sm.ahh[k][j] = ahh_g[(size_t)k * Hn + k0 + j];
    }
    __syncthreads();
    CLUSTER_ARRIVE(); CLUSTER_WAIT();

    // hoisted DSMEM addresses
    const uint32_t pmv_peer = mapa_u32(smem_u32(&sm.pmv[col]), peer);
    const int bx   = tid >> 5;                 // warp id
    const int lane = tid & 31;
    const int h2   = 2 * lane;                 // local h pair base
    const int hg   = k0 + h2;                  // global h pair base
    const uint32_t c1s_peer = (bx < 8)
        ? mapa_u32(smem_u32(&sm.c1s[bx][hg]), peer) : 0u;

    for (int t = 0; t < Tn; t++) {
        if (tid < Xn)      sm.js[tid] = srcp[(b * Tn + t) * Xn + tid];
        else if (tid == 8) sm.cn = cntp[b * Tn + t];
        const float pc = g_Pc[(size_t)(b * Tn + t) * K3 + col];

        // ---- phase A: partial matvec over own k-half ----
        float accw = 0.f, accc = 0.f;
        if (t > 0) {
#pragma unroll
            for (int q = 0; q < 8; q++) {          // k = 0..31 (regs)
                float4 hv = *(const float4*)&sm.h1[q * 4];
                const float* hf = (const float*)&hv;
#pragma unroll
                for (int j = 0; j < 4; j++) {
                    const int k = q * 4 + j;
                    accw = fmaf(hf[j], ww_r[k], accw);
                    accc = fmaf(hf[j], wc_r[k], accc);
                }
            }
#pragma unroll
            for (int q = 0; q < 8; q++) {          // k = 32..63 (smem whhw)
                float4 hv = *(const float4*)&sm.h1[32 + q * 4];
                const float* hf = (const float*)&hv;
#pragma unroll
                for (int j = 0; j < 4; j++) {
                    const int k = q * 4 + j;
                    accw = fmaf(hf[j], sm.whhw_hi[k][col], accw);
                    accc = fmaf(hf[j], wc_r[32 + k], accc);
                }
            }
            st_cluster_f2(pmv_peer, accw, accc);
        }
        CLUSTER_ARRIVE();
        CLUSTER_WAIT();

        // ---- finalize matvec: combine partials ----
        float projw_c = 0.f, gc_c = pc;
        if (t > 0) {
            float2 pp = sm.pmv[col];
            projw_c = accw + pp.x;
            gc_c    = accc + pp.y + pc;
            if (((col & 127) >> 6) == rank)
                g_proj[((size_t)b * Tn + (t - 1)) * K3 + col] = projw_c;
        }
        sm.projw[col] = projw_c;
        sm.gc[col]    = gc_c;
        __syncthreads();

        const int cn = sm.cn;

        // ---- phase B: c1_skip (own h-half, warps 0..7) + gates ----
        if (tid < 256) {
            const int x = bx;
            if (x < cn) {
                const int s = sm.js[x];
                const float* pr = (s == t - 1) ? sm.projw
                                               : (g_proj + ((size_t)b * Tn + s) * K3);
                const float* pw = g_Pw + ((size_t)(b * Tn + t) * Xn + x) * K3;
                float2 r0 = *(const float2*)(pr + hg);
                float2 r1 = *(const float2*)(pr + hg + 128);
                float2 r2 = *(const float2*)(pr + hg + 256);
                float2 w0 = *(const float2*)(pw + hg);
                float2 w1 = *(const float2*)(pw + hg + 128);
                float2 w2 = *(const float2*)(pw + hg + 256);
                float2 cx = *(const float2*)(cs + ((size_t)b * Tn + s) * Hn + hg);
                float c1a, c1b;
                {
                    const float fg = sigm(r0.x + w0.x);
                    const float iw = sigm(r1.x + w1.x);
                    const float gv = tanh_(r2.x + w2.x);
                    c1a = fg * cx.x + iw * gv;
                }
                {
                    const float fg = sigm(r0.y + w0.y);
                    const float iw = sigm(r1.y + w1.y);
                    const float gv = tanh_(r2.y + w2.y);
                    c1b = fg * cx.y + iw * gv;
                }
                *(float2*)&sm.c1s[x][hg] = make_float2(c1a, c1b);
                st_cluster_f2(c1s_peer, c1a, c1b);
            }
        } else if (tid < 320) {
            const int j = tid - 256;
            sm.ig[j] = sigm(sm.gc[k0 + j]);
            sm.og[j] = sigm(sm.gc[k0 + j + 128]);
            sm.gg[j] = tanh_(sm.gc[k0 + j + 256]);
        }
        CLUSTER_ARRIVE();
        CLUSTER_WAIT();

        // ---- phase E: alpha own h-half, full k; 4 warps x 2 x-rows ----
        if (tid < 128) {
            const int w = bx;                   // 0..3 -> x rows (w, w+4)
            if (w < cn) {
                float2 pa = *(const float2*)(g_Pa + (size_t)(b * Tn + t) * Hn + hg);
                unsigned long long pav = pk2(pa.x, pa.y);
                unsigned long long accA = pav, accB = pav;
#pragma unroll 8
                for (int k = 0; k < 128; k++) {
                    unsigned long long av =
                        *(const unsigned long long*)&sm.ahh[k][h2];
                    const float cA = sm.c1s[w][k];
                    const float cB = sm.c1s[w + 4][k];
                    accA = fma2(pk2(cA, cA), av, accA);
                    accB = fma2(pk2(cB, cB), av, accB);
                }
                float a0, a1, b0, b1;
                upk2(accA, a0, a1); upk2(accB, b0, b1);
                *(float2*)&sm.alphas[w][h2]     = make_float2(sigm(a0), sigm(a1));
                *(float2*)&sm.alphas[w + 4][h2] = make_float2(sigm(b0), sigm(b1));
            }
        }
        __syncthreads();

        // ---- phase F: masked softmax merge, own h-half ----
        if (tid < HB) {
            const int j = tid;
            const float e0 = __expf(sm.ig[j]);
            float den = e0;
            float num = sm.gg[j] * e0;
#pragma unroll
            for (int x = 0; x < 8; x++) {
                if (x < cn) {
                    const float ea = __expf(sm.alphas[x][j]);
                    den += ea;
                    num += sm.c1s[x][k0 + j] * ea;
                }
            }
            const float c1  = num / den;
            const float h1v = sm.og[j] * tanh_(c1);
            hs[((size_t)b * Tn + t) * Hn + k0 + j] = h1v;
            cs[((size_t)b * Tn + t) * Hn + k0 + j] = c1;
            sm.h1[j] = h1v;
        }
        __syncthreads();
    }
}

// ---------------------------------------------------------------------
extern "C" void kernel_launch(void* const* d_in, const int* in_sizes, int n_in,
                              void* d_out, int out_size)
{
    int i_src, i_cnt, i_wihc, i_whhc, i_bc, i_aih, i_ahh, i_ab, i_wihw, i_whhw, i_bw;
    if (in_sizes[2] == Bn) {
        i_src = 3;  i_cnt = 4;
        i_wihc = 5; i_whhc = 6; i_bc = 7;
        i_aih = 8;  i_ahh = 9;  i_ab = 10;
        i_wihw = 11; i_whhw = 12; i_bw = 13;
    } else {
        i_wihc = 2; i_whhc = 3; i_bc = 4;
        i_aih = 5;  i_ahh = 6;  i_ab = 7;
        i_wihw = 8; i_whhw = 9; i_bw = 10;
        i_src = 12; i_cnt = 13;
    }

    const float* inp        = (const float*)d_in[0];
    const float* skip_words = (const float*)d_in[1];
    const int*   srcp       = (const int*)d_in[i_src];
    const int*   cntp       = (const int*)d_in[i_cnt];
    const float* wihc = (const float*)d_in[i_wihc];
    const float* whhc = (const float*)d_in[i_whhc];
    const float* bc   = (const float*)d_in[i_bc];
    const float* aih  = (const float*)d_in[i_aih];
    const float* ahh  = (const float*)d_in[i_ahh];
    const float* ab   = (const float*)d_in[i_ab];
    const float* wihw = (const float*)d_in[i_wihw];
    const float* whhw = (const float*)d_in[i_whhw];
    const float* bw   = (const float*)d_in[i_bw];

    float *Pw, *Pc, *Pa;
    cudaGetSymbolAddress((void**)&Pw, g_Pw);
    cudaGetSymbolAddress((void**)&Pc, g_Pc);
    cudaGetSymbolAddress((void**)&Pa, g_Pa);

    // Input projections
    gemm128<<<dim3(K3 / 128, (Bn * Tn * Xn) / 128), 256>>>(skip_words, wihw, bw, Pw, K3);
    gemm128<<<dim3(K3 / 128, (Bn * Tn) / 128),      256>>>(inp,        wihc, bc, Pc, K3);
    gemm128<<<dim3(Hn / 128, (Bn * Tn) / 128),      256>>>(inp,        aih,  ab, Pa, Hn);

    static int attr_done = 0;
    if (!attr_done) {
        cudaFuncSetAttribute(lattice_recurrent,
                             cudaFuncAttributeMaxDynamicSharedMemorySize,
                             (int)sizeof(RecSmem));
        attr_done = 1;
    }
    // 2 CTAs per batch (cluster), 128 CTAs total
    lattice_recurrent<<<Bn * 2, 384, sizeof(RecSmem)>>>(whhw, whhc, ahh,
                                                        srcp, cntp, (float*)d_out);
}

// round 7
// speedup vs baseline: 4.4546x; 1.1112x over previous
#include <cuda_runtime.h>
#include <math.h>
#include <stdint.h>

#define Bn 64
#define Tn 512
#define Xn 8
#define Hn 128
#define K3 384   // 3*H
#define HB 64    // half of H

// -------- device scratch (allocation-free) --------
__device__ float g_Pw[(size_t)Bn * Tn * Xn * K3];  // [B,T,X,3H]
__device__ float g_Pc[(size_t)Bn * Tn * K3];       // [B,T,3H]
__device__ float g_Pa[(size_t)Bn * Tn * Hn];       // [B,T,H]
__device__ float g_proj[(size_t)Bn * Tn * K3];     // proj[b][s] = h1(s) @ w_hh_w

// -------- asm helpers --------
__device__ __forceinline__ void cpa16(uint32_t s, const void* g) {
    asm volatile("cp.async.cg.shared.global [%0], [%1], 16;" :: "r"(s), "l"(g));
}
__device__ __forceinline__ void cp_commit() { asm volatile("cp.async.commit_group;"); }
template<int N> __device__ __forceinline__ void cp_wait() {
    asm volatile("cp.async.wait_group %0;" :: "n"(N));
}
__device__ __forceinline__ unsigned long long pk2(float x, float y) {
    unsigned long long r;
    asm("mov.b64 %0, {%1, %2};" : "=l"(r) : "f"(x), "f"(y));
    return r;
}
__device__ __forceinline__ void upk2(unsigned long long v, float& x, float& y) {
    asm("mov.b64 {%0, %1}, %2;" : "=f"(x), "=f"(y) : "l"(v));
}
__device__ __forceinline__ unsigned long long fma2(
    unsigned long long a, unsigned long long b, unsigned long long c) {
    unsigned long long d;
    asm("fma.rn.f32x2 %0, %1, %2, %3;" : "=l"(d) : "l"(a), "l"(b), "l"(c));
    return d;
}
__device__ __forceinline__ uint32_t smem_u32(const void* p) {
    return (uint32_t)__cvta_generic_to_shared(p);
}
__device__ __forceinline__ uint32_t mapa_u32(uint32_t a, uint32_t rank) {
    uint32_t d;
    asm("mapa.shared::cluster.u32 %0, %1, %2;" : "=r"(d) : "r"(a), "r"(rank));
    return d;
}
__device__ __forceinline__ void st_cluster_f2(uint32_t a, float x, float y) {
    asm volatile("st.shared::cluster.v2.f32 [%0], {%1, %2};"
                 :: "r"(a), "f"(x), "f"(y) : "memory");
}
__device__ __forceinline__ void mbar_init(uint32_t a, uint32_t cnt) {
    asm volatile("mbarrier.init.shared.b64 [%0], %1;" :: "r"(a), "r"(cnt) : "memory");
}
__device__ __forceinline__ void mbar_arrive_remote(uint32_t ra) {
    asm volatile("mbarrier.arrive.release.cluster.shared::cluster.b64 _, [%0];"
                 :: "r"(ra) : "memory");
}
__device__ __forceinline__ void mbar_wait(uint32_t a, uint32_t parity) {
    asm volatile(
        "{\n\t.reg .pred P1;\n\t"
        "WL%=:\n\t"
        "mbarrier.try_wait.parity.acquire.cluster.shared::cta.b64 P1, [%0], %1;\n\t"
        "@!P1 bra WL%=;\n\t"
        "}"
        :: "r"(a), "r"(parity) : "memory");
}
#define CLUSTER_ARRIVE() asm volatile("barrier.cluster.arrive.aligned;" ::: "memory")
#define CLUSTER_WAIT()   asm volatile("barrier.cluster.wait.aligned;"   ::: "memory")

__device__ __forceinline__ float sigm(float x) { return 1.f / (1.f + __expf(-x)); }
__device__ __forceinline__ float tanh_(float x) {
    float e = __expf(2.f * x);
    return 1.f - 2.f / (e + 1.f);
}

// ---------------------------------------------------------------------
// SGEMM with fma.rn.f32x2 (unchanged)
// ---------------------------------------------------------------------
__global__ __launch_bounds__(256) void gemm128(
    const float* __restrict__ A, const float* __restrict__ W,
    const float* __restrict__ bias, float* __restrict__ C, int N)
{
    __shared__ float As[2][8][128];
    __shared__ float Bs[2][8][128];

    const int tid = threadIdx.x;
    const int m0 = blockIdx.y * 128;
    const int n0 = blockIdx.x * 128;

    const int arow = tid >> 1;
    const int ak4  = (tid & 1) << 2;
    const int brow = tid >> 5;
    const int bc4  = (tid & 31) << 2;
    const int ty   = tid >> 4;
    const int tx   = tid & 15;

    const float* Ag = A + (size_t)(m0 + arow) * 128 + ak4;
    const float* Wg = W + (size_t)brow * N + n0 + bc4;

    unsigned long long acc2[8][4];
#pragma unroll
    for (int i = 0; i < 8; i++)
#pragma unroll
        for (int j = 0; j < 4; j++) acc2[i][j] = 0ull;

    float4 ra = *(const float4*)Ag;
    float4 rb = *(const float4*)Wg;
    As[0][ak4 + 0][arow] = ra.x; As[0][ak4 + 1][arow] = ra.y;
    As[0][ak4 + 2][arow] = ra.z; As[0][ak4 + 3][arow] = ra.w;
    *(float4*)&Bs[0][brow][bc4] = rb;
    __syncthreads();

    int p = 0;
    for (int kc = 8; kc <= 128; kc += 8) {
        const bool more = (kc < 128);
        if (more) {
            ra = *(const float4*)(Ag + kc);
            rb = *(const float4*)(Wg + (size_t)kc * N);
        }
#pragma unroll
        for (int k = 0; k < 8; k++) {
            float af[8], bf[8];
            *(float4*)&af[0] = *(const float4*)&As[p][k][ty * 4];
            *(float4*)&af[4] = *(const float4*)&As[p][k][ty * 4 + 64];
            *(float4*)&bf[0] = *(const float4*)&Bs[p][k][tx * 4];
            *(float4*)&bf[4] = *(const float4*)&Bs[p][k][tx * 4 + 64];
            unsigned long long bd[4];
            bd[0] = pk2(bf[0], bf[1]); bd[1] = pk2(bf[2], bf[3]);
            bd[2] = pk2(bf[4], bf[5]); bd[3] = pk2(bf[6], bf[7]);
#pragma unroll
            for (int i = 0; i < 8; i++) {
                unsigned long long ad = pk2(af[i], af[i]);
#pragma unroll
                for (int j = 0; j < 4; j++) acc2[i][j] = fma2(ad, bd[j], acc2[i][j]);
            }
        }
        if (more) {
            p ^= 1;
            As[p][ak4 + 0][arow] = ra.x; As[p][ak4 + 1][arow] = ra.y;
            As[p][ak4 + 2][arow] = ra.z; As[p][ak4 + 3][arow] = ra.w;
            *(float4*)&Bs[p][brow][bc4] = rb;
            __syncthreads();
        }
    }

    float bv[8];
#pragma unroll
    for (int j = 0; j < 4; j++) {
        bv[j]     = bias[n0 + tx * 4 + j];
        bv[j + 4] = bias[n0 + tx * 4 + 64 + j];
    }
#pragma unroll
    for (int i = 0; i < 8; i++) {
        const int r = m0 + ty * 4 + (i & 3) + ((i >> 2) << 6);
        float a0, a1, a2, a3, a4, a5, a6, a7;
        upk2(acc2[i][0], a0, a1); upk2(acc2[i][1], a2, a3);
        upk2(acc2[i][2], a4, a5); upk2(acc2[i][3], a6, a7);
        float4 o0, o1;
        o0.x = a0 + bv[0]; o0.y = a1 + bv[1]; o0.z = a2 + bv[2]; o0.w = a3 + bv[3];
        o1.x = a4 + bv[4]; o1.y = a5 + bv[5]; o1.z = a6 + bv[6]; o1.w = a7 + bv[7];
        *(float4*)&C[(size_t)r * N + n0 + tx * 4]      = o0;
        *(float4*)&C[(size_t)r * N + n0 + tx * 4 + 64] = o1;
    }
}

// ---------------------------------------------------------------------
// Recurrent scan: 2-CTA cluster per batch; mbarrier sync + cp.async
// prefetch of all per-step global reads.
// ---------------------------------------------------------------------
struct alignas(16) RecSmem {
    float whhw_hi[32][K3];     // 49152 : whhw rows k0+32..k0+63
    float ahh[Hn][HB];         // 32768 : a_hh[:, k0..k0+64)
    float2 pmv[K3];            //  3072 : peer partials (only own-half cols used)
    float projw[K3];           //  1536 : own-half cols valid
    float gc[K3];              //  1536 : own-half cols valid
    float c1s[Xn][Hn];         //  4096
    float alphas[Xn][HB];      //  2048
    float prbuf[Xn][3][HB];    //  6144 : proj gather staging (own half)
    float pwbuf[Xn][3][HB];    //  6144 : Pw staging (own half)
    float cxbuf[Xn][HB];       //  2048 : cs gather staging (own half)
    float pabuf[HB];           //   256
    float ig[HB], og[HB], gg[HB];  // 768
    float h1[HB];              //   256
    float cprev[HB];           //   256 : own-half c1(t-1)
    int   jsb[2][Xn];
    int   cnb[2];
    unsigned long long mbar[2];   // [0]=pmv, [1]=c1s
};

__global__ __launch_bounds__(384, 1) __cluster_dims__(2, 1, 1)
void lattice_recurrent(
    const float* __restrict__ whhw,   // [128,384]
    const float* __restrict__ whhc,   // [128,384]
    const float* __restrict__ ahh_g,  // [128,128]
    const int*   __restrict__ srcp,   // [B,T,X]
    const int*   __restrict__ cntp,   // [B,T]
    float* __restrict__ out)          // hs then cs, each [B,T,H]
{
    extern __shared__ unsigned char smem_raw[];
    RecSmem& sm = *reinterpret_cast<RecSmem*>(smem_raw);

    const int rank = blockIdx.x & 1;
    const int b    = blockIdx.x >> 1;
    const int peer = rank ^ 1;
    const int tid  = threadIdx.x;
    const int col  = tid;
    const int k0   = rank * HB;

    float* hs = out;
    float* cs = out + (size_t)Bn * Tn * Hn;

    // ---- one-time init ----
    if (tid == 0) {
        mbar_init(smem_u32(&sm.mbar[0]), 1);
        mbar_init(smem_u32(&sm.mbar[1]), 1);
    }
    float wc_r[64];   // whhc[k0+k][col]
    float ww_r[32];   // whhw[k0+k][col], k<32
#pragma unroll
    for (int k = 0; k < 64; k++) wc_r[k] = whhc[(size_t)(k0 + k) * K3 + col];
#pragma unroll
    for (int k = 0; k < 32; k++) ww_r[k] = whhw[(size_t)(k0 + k) * K3 + col];
    for (int i = tid; i < 32 * K3; i += 384) {
        int r = i / K3, c = i % K3;
        sm.whhw_hi[r][c] = whhw[(size_t)(k0 + 32 + r) * K3 + c];
    }
    for (int i = tid; i < Hn * HB; i += 384) {
        int k = i / HB, j = i % HB;
        sm.ahh[k][j] = ahh_g[(size_t)k * Hn + k0 + j];
    }
    if (tid < Xn)       sm.jsb[0][tid] = srcp[(b * Tn) * Xn + tid];
    else if (tid == 8)  sm.cnb[0] = cntp[b * Tn];
    __syncthreads();
    CLUSTER_ARRIVE(); CLUSTER_WAIT();   // peer mbars + weights ready

    // hoisted addresses / ids
    const int bx   = tid >> 5;
    const int lane = tid & 31;
    const int h2   = 2 * lane;
    const int hg   = k0 + h2;
    const bool own_col  = (((col & 127) >> 6) == rank);
    const uint32_t pmv_peer = mapa_u32(smem_u32(&sm.pmv[col]), peer);
    const uint32_t c1s_peer = (bx < 8)
        ? mapa_u32(smem_u32(&sm.c1s[bx][hg]), peer) : 0u;
    const uint32_t mb0_l = smem_u32(&sm.mbar[0]);
    const uint32_t mb1_l = smem_u32(&sm.mbar[1]);
    const uint32_t mb0_p = mapa_u32(mb0_l, peer);
    const uint32_t mb1_p = mapa_u32(mb1_l, peer);
    const uint32_t d_cx = smem_u32(sm.cxbuf);
    const uint32_t d_pr = smem_u32(sm.prbuf);
    const uint32_t d_pw = smem_u32(sm.pwbuf);
    const uint32_t d_pa = smem_u32(sm.pabuf);

    for (int t = 0; t < Tn; t++) {
        const int pr = t & 1;
        const size_t bT = (size_t)b * Tn + t;
        const int cn = sm.cnb[pr];

        // early LDGs (latency hidden behind phase A)
        const float pc = g_Pc[bT * K3 + col];
        int jv = 0;
        if (t + 1 < Tn && tid < 9)
            jv = (tid < 8) ? srcp[(bT + 1) * Xn + tid] : cntp[bT + 1];

        // ---- prefetch all per-step global reads into smem ----
        for (int i = tid; i < 912; i += 384) {
            if (i < 128) {
                int x = i >> 4, c = (i & 15) << 2;
                int s = sm.jsb[pr][x];
                cpa16(d_cx + (((x << 6) + c) << 2),
                      cs + ((size_t)b * Tn + s) * Hn + k0 + c);
            } else if (i < 512) {
                int r = i - 128;
                int u = r >> 4, c = (r & 15) << 2;
                int x = u / 3, g = u - x * 3;
                int s = sm.jsb[pr][x];
                cpa16(d_pr + (((u << 6) + c) << 2),
                      g_proj + ((size_t)b * Tn + s) * K3 + g * 128 + k0 + c);
            } else if (i < 896) {
                int r = i - 512;
                int u = r >> 4, c = (r & 15) << 2;
                int x = u / 3, g = u - x * 3;
                cpa16(d_pw + (((u << 6) + c) << 2),
                      g_Pw + (bT * Xn + x) * K3 + g * 128 + k0 + c);
            } else {
                int c = (i - 896) << 2;
                cpa16(d_pa + (c << 2), g_Pa + bT * Hn + k0 + c);
            }
        }
        cp_commit();

        // ---- phase A: partial matvec over own k-half ----
        float accw = 0.f, accc = 0.f;
        if (t > 0) {
            float aw0 = 0.f, aw1 = 0.f, ac0 = 0.f, ac1 = 0.f;
#pragma unroll
            for (int q = 0; q < 8; q++) {          // k = 0..31 (regs)
                float4 hv = *(const float4*)&sm.h1[q * 4];
                const float* hf = (const float*)&hv;
#pragma unroll
                for (int j = 0; j < 4; j++) {
                    const int k = q * 4 + j;
                    if (q & 1) { aw1 = fmaf(hf[j], ww_r[k], aw1);
                                 ac1 = fmaf(hf[j], wc_r[k], ac1); }
                    else       { aw0 = fmaf(hf[j], ww_r[k], aw0);
                                 ac0 = fmaf(hf[j], wc_r[k], ac0); }
                }
            }
#pragma unroll
            for (int q = 0; q < 8; q++) {          // k = 32..63 (smem whhw)
                float4 hv = *(const float4*)&sm.h1[32 + q * 4];
                const float* hf = (const float*)&hv;
#pragma unroll
                for (int j = 0; j < 4; j++) {
                    const int k = q * 4 + j;
                    if (q & 1) { aw1 = fmaf(hf[j], sm.whhw_hi[k][col], aw1);
                                 ac1 = fmaf(hf[j], wc_r[32 + k], ac1); }
                    else       { aw0 = fmaf(hf[j], sm.whhw_hi[k][col], aw0);
                                 ac0 = fmaf(hf[j], wc_r[32 + k], ac0); }
                }
            }
            accw = aw0 + aw1; accc = ac0 + ac1;
            if (!own_col) st_cluster_f2(pmv_peer, accw, accc);
        }
        __syncthreads();                 // local stores + pmv sends done
        if (t > 0) {
            if (tid == 0) mbar_arrive_remote(mb0_p);
            mbar_wait(mb0_l, (t - 1) & 1);
        }
        cp_wait<0>();                    // my prefetch chunks landed

        // ---- finalize matvec (own-half cols only) ----
        if (own_col) {
            float projw_c = 0.f, gc_c = pc;
            if (t > 0) {
                float2 pp = sm.pmv[col];
                projw_c = accw + pp.x;
                gc_c    = accc + pp.y + pc;
                g_proj[((size_t)b * Tn + (t - 1)) * K3 + col] = projw_c;
            }
            sm.projw[col] = projw_c;
            sm.gc[col]    = gc_c;
        }
        __syncthreads();                 // projw/gc + staged data visible

        // ---- phase B: c1_skip (own h-half, warps 0..7) + gates ----
        if (tid < 256) {
            const int x = bx;
            if (x < cn) {
                const int s = sm.jsb[pr][x];
                const bool prev = (s == t - 1);
                float2 r0 = prev ? *(const float2*)&sm.projw[hg]
                                 : *(const float2*)&sm.prbuf[x][0][h2];
                float2 r1 = prev ? *(const float2*)&sm.projw[hg + 128]
                                 : *(const float2*)&sm.prbuf[x][1][h2];
                float2 r2 = prev ? *(const float2*)&sm.projw[hg + 256]
                                 : *(const float2*)&sm.prbuf[x][2][h2];
                float2 w0 = *(const float2*)&sm.pwbuf[x][0][h2];
                float2 w1 = *(const float2*)&sm.pwbuf[x][1][h2];
                float2 w2 = *(const float2*)&sm.pwbuf[x][2][h2];
                float2 cx = prev ? *(const float2*)&sm.cprev[h2]
                                 : *(const float2*)&sm.cxbuf[x][h2];
                float c1a, c1b;
                {
                    const float fg = sigm(r0.x + w0.x);
                    const float iw = sigm(r1.x + w1.x);
                    const float gv = tanh_(r2.x + w2.x);
                    c1a = fg * cx.x + iw * gv;
                }
                {
                    const float fg = sigm(r0.y + w0.y);
                    const float iw = sigm(r1.y + w1.y);
                    const float gv = tanh_(r2.y + w2.y);
                    c1b = fg * cx.y + iw * gv;
                }
                *(float2*)&sm.c1s[x][hg] = make_float2(c1a, c1b);
                st_cluster_f2(c1s_peer, c1a, c1b);
            }
        } else if (tid < 320) {
            const int j = tid - 256;
            sm.ig[j] = sigm(sm.gc[k0 + j]);
            sm.og[j] = sigm(sm.gc[k0 + j + 128]);
            sm.gg[j] = tanh_(sm.gc[k0 + j + 256]);
        }
        __syncthreads();                 // c1s local + remote sends done
        if (tid == 0) mbar_arrive_remote(mb1_p);
        mbar_wait(mb1_l, t & 1);

        // ---- phase E: alpha own h-half, full k; 4 warps x 2 x-rows ----
        if (tid < 128) {
            const int w = bx;
            if (w < cn) {
                float2 pa = *(const float2*)&sm.pabuf[h2];
                unsigned long long pav = pk2(pa.x, pa.y);
                unsigned long long accA = pav, accB = pav;
#pragma unroll 8
                for (int k = 0; k < 128; k++) {
                    unsigned long long av =
                        *(const unsigned long long*)&sm.ahh[k][h2];
                    const float cA = sm.c1s[w][k];
                    const float cB = sm.c1s[w + 4][k];
                    accA = fma2(pk2(cA, cA), av, accA);
                    accB = fma2(pk2(cB, cB), av, accB);
                }
                float a0, a1, b0, b1;
                upk2(accA, a0, a1); upk2(accB, b0, b1);
                *(float2*)&sm.alphas[w][h2]     = make_float2(sigm(a0), sigm(a1));
                *(float2*)&sm.alphas[w + 4][h2] = make_float2(sigm(b0), sigm(b1));
            }
        }
        __syncthreads();

        // ---- phase F: masked softmax merge, own h-half ----
        if (tid < HB) {
            const int j = tid;
            const float e0 = __expf(sm.ig[j]);
            float den = e0;
            float num = sm.gg[j] * e0;
#pragma unroll
            for (int x = 0; x < 8; x++) {
                if (x < cn) {
                    const float ea = __expf(sm.alphas[x][j]);
                    den += ea;
                    num += sm.c1s[x][k0 + j] * ea;
                }
            }
            const float c1  = num / den;
            const float h1v = sm.og[j] * tanh_(c1);
            hs[bT * Hn + k0 + j] = h1v;
            cs[bT * Hn + k0 + j] = c1;
            sm.h1[j]    = h1v;
            sm.cprev[j] = c1;
        }
        // stage next step's js/cn
        if (t + 1 < Tn && tid < 9) {
            if (tid < 8) sm.jsb[pr ^ 1][tid] = jv;
            else         sm.cnb[pr ^ 1] = jv;
        }
        __syncthreads();
    }
}

// ---------------------------------------------------------------------
extern "C" void kernel_launch(void* const* d_in, const int* in_sizes, int n_in,
                              void* d_out, int out_size)
{
    int i_src, i_cnt, i_wihc, i_whhc, i_bc, i_aih, i_ahh, i_ab, i_wihw, i_whhw, i_bw;
    if (in_sizes[2] == Bn) {
        i_src = 3;  i_cnt = 4;
        i_wihc = 5; i_whhc = 6; i_bc = 7;
        i_aih = 8;  i_ahh = 9;  i_ab = 10;
        i_wihw = 11; i_whhw = 12; i_bw = 13;
    } else {
        i_wihc = 2; i_whhc = 3; i_bc = 4;
        i_aih = 5;  i_ahh = 6;  i_ab = 7;
        i_wihw = 8; i_whhw = 9; i_bw = 10;
        i_src = 12; i_cnt = 13;
    }

    const float* inp        = (const float*)d_in[0];
    const float* skip_words = (const float*)d_in[1];
    const int*   srcp       = (const int*)d_in[i_src];
    const int*   cntp       = (const int*)d_in[i_cnt];
    const float* wihc = (const float*)d_in[i_wihc];
    const float* whhc = (const float*)d_in[i_whhc];
    const float* bc   = (const float*)d_in[i_bc];
    const float* aih  = (const float*)d_in[i_aih];
    const float* ahh  = (const float*)d_in[i_ahh];
    const float* ab   = (const float*)d_in[i_ab];
    const float* wihw = (const float*)d_in[i_wihw];
    const float* whhw = (const float*)d_in[i_whhw];
    const float* bw   = (const float*)d_in[i_bw];

    float *Pw, *Pc, *Pa;
    cudaGetSymbolAddress((void**)&Pw, g_Pw);
    cudaGetSymbolAddress((void**)&Pc, g_Pc);
    cudaGetSymbolAddress((void**)&Pa, g_Pa);

    // Input projections
    gemm128<<<dim3(K3 / 128, (Bn * Tn * Xn) / 128), 256>>>(skip_words, wihw, bw, Pw, K3);
    gemm128<<<dim3(K3 / 128, (Bn * Tn) / 128),      256>>>(inp,        wihc, bc, Pc, K3);
    gemm128<<<dim3(Hn / 128, (Bn * Tn) / 128),      256>>>(inp,        aih,  ab, Pa, Hn);

    static int attr_done = 0;
    if (!attr_done) {
        cudaFuncSetAttribute(lattice_recurrent,
                             cudaFuncAttributeMaxDynamicSharedMemorySize,
                             (int)sizeof(RecSmem));
        attr_done = 1;
    }
    lattice_recurrent<<<Bn * 2, 384, sizeof(RecSmem)>>>(whhw, whhc, ahh,
                                                        srcp, cntp, (float*)d_out);
}